// round 5
// baseline (speedup 1.0000x reference)
#include <cuda_runtime.h>
#include <math.h>

#define Bb 16
#define Ss 1024
#define Dd 512
#define Hh 512
#define Uu 512
#define MR (Bb*Ss)        // 16384 rows
#define G4U (4*Uu)        // 2048

// ---------------- scratch (device globals; no allocations allowed) ----------
__device__ float d_q[MR*Hh];
__device__ float d_k[MR*Hh];
__device__ float d_v[MR*Hh];
__device__ float d_scores[(size_t)Bb*Ss*Ss];
__device__ float d_ctx[MR*Hh];
__device__ float d_proj[MR*Uu];
__device__ float d_y1[MR*Uu];
__device__ float d_xp[(size_t)MR*G4U];
__device__ float d_hs[MR*Uu];
__device__ float d_hbuf[2][Bb*Uu];
__device__ int   d_flags[128];

// ---------------- generic fp32 SGEMM: C = alpha * A * op(B) (+bias) ---------
template<int TB>
__global__ __launch_bounds__(256) void sgemm(
    const float* __restrict__ Ag, const float* __restrict__ Bg,
    float* __restrict__ Cg, const float* __restrict__ bias,
    int M, int N, int K, long sA, long sB, long sC, float alpha)
{
    const float* A  = Ag + (long)blockIdx.z * sA;
    const float* Bm = Bg + (long)blockIdx.z * sB;
    float*       C  = Cg + (long)blockIdx.z * sC;

    __shared__ float As[8][128];
    __shared__ float Bs[8][128];

    int tid = threadIdx.x;
    int m0 = blockIdx.y * 128, n0 = blockIdx.x * 128;
    int tx = tid & 15, ty = tid >> 4;

    float acc[8][8];
#pragma unroll
    for (int i = 0; i < 8; i++)
#pragma unroll
        for (int j = 0; j < 8; j++) acc[i][j] = 0.f;

    int arow = tid >> 1, akc = (tid & 1) * 4;

    float4 av, bv;
    av = *(const float4*)&A[(long)(m0 + arow) * K + akc];
    if (TB == 0)
        bv = *(const float4*)&Bm[(long)(tid >> 5) * N + n0 + (tid & 31) * 4];
    else
        bv = *(const float4*)&Bm[(long)(n0 + (tid >> 1)) * K + (tid & 1) * 4];

    for (int k0 = 0; k0 < K; k0 += 8) {
        As[akc + 0][arow] = av.x; As[akc + 1][arow] = av.y;
        As[akc + 2][arow] = av.z; As[akc + 3][arow] = av.w;
        if (TB == 0) {
            *(float4*)&Bs[tid >> 5][(tid & 31) * 4] = bv;
        } else {
            int bn = tid >> 1, c0 = (tid & 1) * 4;
            Bs[c0 + 0][bn] = bv.x; Bs[c0 + 1][bn] = bv.y;
            Bs[c0 + 2][bn] = bv.z; Bs[c0 + 3][bn] = bv.w;
        }
        __syncthreads();

        int k1 = k0 + 8;
        if (k1 < K) {
            av = *(const float4*)&A[(long)(m0 + arow) * K + k1 + akc];
            if (TB == 0)
                bv = *(const float4*)&Bm[(long)(k1 + (tid >> 5)) * N + n0 + (tid & 31) * 4];
            else
                bv = *(const float4*)&Bm[(long)(n0 + (tid >> 1)) * K + k1 + (tid & 1) * 4];
        }

#pragma unroll
        for (int k = 0; k < 8; k++) {
            float a[8], b[8];
            *(float4*)&a[0] = *(const float4*)&As[k][ty * 4];
            *(float4*)&a[4] = *(const float4*)&As[k][64 + ty * 4];
            *(float4*)&b[0] = *(const float4*)&Bs[k][tx * 4];
            *(float4*)&b[4] = *(const float4*)&Bs[k][64 + tx * 4];
#pragma unroll
            for (int i = 0; i < 8; i++)
#pragma unroll
                for (int j = 0; j < 8; j++) acc[i][j] += a[i] * b[j];
        }
        __syncthreads();
    }

#pragma unroll
    for (int i = 0; i < 8; i++) {
        int r = m0 + ((i < 4) ? (ty * 4 + i) : (64 + ty * 4 + i - 4));
#pragma unroll
        for (int jh = 0; jh < 2; jh++) {
            int c = n0 + jh * 64 + tx * 4;
            float4 o;
            o.x = alpha * acc[i][jh * 4 + 0];
            o.y = alpha * acc[i][jh * 4 + 1];
            o.z = alpha * acc[i][jh * 4 + 2];
            o.w = alpha * acc[i][jh * 4 + 3];
            if (bias) {
                o.x += bias[c + 0]; o.y += bias[c + 1];
                o.z += bias[c + 2]; o.w += bias[c + 3];
            }
            *(float4*)&C[(long)r * N + c] = o;
        }
    }
}

// ---------------- softmax over rows of length 1024 ---------------------------
__global__ __launch_bounds__(256) void softmax_k(float* __restrict__ s)
{
    __shared__ float red[8];
    long row = blockIdx.x;
    float* p = s + row * 1024;
    int tid = threadIdx.x;
    float4 v = ((float4*)p)[tid];

    float m = fmaxf(fmaxf(v.x, v.y), fmaxf(v.z, v.w));
#pragma unroll
    for (int o = 16; o; o >>= 1) m = fmaxf(m, __shfl_xor_sync(~0u, m, o));
    if ((tid & 31) == 0) red[tid >> 5] = m;
    __syncthreads();
    m = red[0];
#pragma unroll
    for (int i = 1; i < 8; i++) m = fmaxf(m, red[i]);

    v.x = expf(v.x - m); v.y = expf(v.y - m);
    v.z = expf(v.z - m); v.w = expf(v.w - m);
    float su = v.x + v.y + v.z + v.w;
#pragma unroll
    for (int o = 16; o; o >>= 1) su += __shfl_xor_sync(~0u, su, o);
    __syncthreads();
    if ((tid & 31) == 0) red[tid >> 5] = su;
    __syncthreads();
    su = 0.f;
#pragma unroll
    for (int i = 0; i < 8; i++) su += red[i];
    float inv = 1.f / su;
    v.x *= inv; v.y *= inv; v.z *= inv; v.w *= inv;
    ((float4*)p)[tid] = v;
}

// ---------------- fused residual add + LayerNorm (row len 512) --------------
__global__ __launch_bounds__(128) void ln_add_k(
    const float* __restrict__ a, const float* __restrict__ b,
    const float* __restrict__ gamma, const float* __restrict__ beta,
    float* __restrict__ out)
{
    __shared__ float red[4];
    long row = blockIdx.x;
    int tid = threadIdx.x;
    float4 x = ((const float4*)(a + row * 512))[tid];
    float4 y = ((const float4*)(b + row * 512))[tid];
    x.x += y.x; x.y += y.y; x.z += y.z; x.w += y.w;

    float su = x.x + x.y + x.z + x.w;
#pragma unroll
    for (int o = 16; o; o >>= 1) su += __shfl_xor_sync(~0u, su, o);
    if ((tid & 31) == 0) red[tid >> 5] = su;
    __syncthreads();
    su = red[0] + red[1] + red[2] + red[3];
    float mu = su * (1.f / 512.f);

    float4 dx;
    dx.x = x.x - mu; dx.y = x.y - mu; dx.z = x.z - mu; dx.w = x.w - mu;
    float sq = dx.x * dx.x + dx.y * dx.y + dx.z * dx.z + dx.w * dx.w;
#pragma unroll
    for (int o = 16; o; o >>= 1) sq += __shfl_xor_sync(~0u, sq, o);
    __syncthreads();
    if ((tid & 31) == 0) red[tid >> 5] = sq;
    __syncthreads();
    sq = red[0] + red[1] + red[2] + red[3];
    float inv = rsqrtf(sq * (1.f / 512.f) + 1e-3f);

    float4 g = ((const float4*)gamma)[tid];
    float4 bt = ((const float4*)beta)[tid];
    float4 o4;
    o4.x = g.x * dx.x * inv + bt.x;
    o4.y = g.y * dx.y * inv + bt.y;
    o4.z = g.z * dx.z * inv + bt.z;
    o4.w = g.w * dx.w * inv + bt.w;
    ((float4*)(out + row * 512))[tid] = o4;
}

// ---------------- reset for persistent LSTM sync state ----------------------
__global__ void reset_k()
{
    int tid = threadIdx.x + blockIdx.x * blockDim.x;
    if (tid < Bb * Uu) { d_hbuf[0][tid] = 0.f; d_hbuf[1][tid] = 0.f; }
    if (tid < 128) d_flags[tid] = 0;
}

// ---------------- persistent LSTM scan --------------------------------------
// 128 CTAs x 256 threads (1 CTA/SM, single wave).
// CTA owns u's [cta*4, cta*4+4) -> 16 gate cols, ALL 16 batches.
// R slice k-major in smem Rs[16 cols][516]; h staged naturally h_s[16 b][516].
// Thread tile: 4 cols x 4 batches x 32 k  (8 FMA per LDS.128).
// Flag-array barrier (no atomics), one per step; double-buffered h.
#define LSTM_NCTA 128
#define LSTM_STRIDE 516
#define LSTM_DSMEM (2 * 16 * LSTM_STRIDE * 4)   // Rs + h_s = 66048 B

__global__ __launch_bounds__(256) void lstm_k(
    const float* __restrict__ xp, const float* __restrict__ R,
    float* __restrict__ hs)
{
    extern __shared__ float sm[];
    float* Rs  = sm;                       // [16][516] k-major
    float* h_s = sm + 16 * LSTM_STRIDE;    // [16][516] k-major
    __shared__ float z_part[16][16][16];   // [ks][col][b]
    __shared__ float z_s[16][16];          // [col][b]
    __shared__ float c_s[4][17];

    const int tid = threadIdx.x;
    const int cta = blockIdx.x;
    const int u0  = cta * 4;

    // Load R slice transposed to k-major: Rs[c][k], c = g*4+du -> col g*512+u0+du
    for (int idx = tid; idx < 8192; idx += 256) {
        int c = idx & 15, k = idx >> 4;
        Rs[c * LSTM_STRIDE + k] = R[(long)k * 2048 + (c >> 2) * 512 + u0 + (c & 3)];
    }
    if (tid < 64) c_s[tid >> 4][tid & 15] = 0.f;

    const int cq = tid & 3;          // col quad: cols cq*4 .. cq*4+3
    const int bq = (tid >> 2) & 3;   // batch quad: b bq*4 .. bq*4+3
    const int ks = tid >> 4;         // 16 slices of 32 k
    const float* rp = Rs + (cq * 4) * LSTM_STRIDE + ks * 32;
    const float* hp = h_s + (bq * 4) * LSTM_STRIDE + ks * 32;

    // reducer identity: one (col, batch) per thread
    const int rc = tid >> 4;         // col 0..15
    const int rb = tid & 15;         // batch 0..15
    const float* xp_t = xp + (long)rb * Ss * 2048
                           + (rc >> 2) * 512 + u0 + (rc & 3);

    __syncthreads();

    for (int t = 0; t < 1024; t++) {
        // prefetch xp operand for this step (independent of barrier)
        float xv = __ldg(xp_t + (long)t * 2048);

        // ---- wait for all step-(t-1) h writes (flag array, no atomics) ----
        if (t > 0) {
            if (tid < LSTM_NCTA) {
                while (((volatile int*)d_flags)[tid] < t) __nanosleep(20);
                __threadfence();
            }
            __syncthreads();
        }

        // ---- stage h_{t-1} (all 16 batches = 2048 float4) into smem ----
        {
            const float4* hg = (const float4*)(d_hbuf[(t + 1) & 1]);
#pragma unroll
            for (int j = 0; j < 8; j++) {
                int i = tid + j * 256;          // 0..2047 float4
                float4 v = __ldcg(hg + i);
                int b = i >> 7, k4 = (i & 127) * 4;
                *(float4*)(h_s + b * LSTM_STRIDE + k4) = v;
            }
        }
        __syncthreads();

        // ---- partial dots: 4 cols x 4 batches x 32 k per thread ----
        {
            float acc[4][4];
#pragma unroll
            for (int j = 0; j < 4; j++)
#pragma unroll
                for (int i = 0; i < 4; i++) acc[j][i] = 0.f;

#pragma unroll 2
            for (int k4 = 0; k4 < 8; k4++) {
                int k = k4 * 4;
                float4 r0 = *(const float4*)(rp + 0 * LSTM_STRIDE + k);
                float4 r1 = *(const float4*)(rp + 1 * LSTM_STRIDE + k);
                float4 r2 = *(const float4*)(rp + 2 * LSTM_STRIDE + k);
                float4 r3 = *(const float4*)(rp + 3 * LSTM_STRIDE + k);
                float4 h0 = *(const float4*)(hp + 0 * LSTM_STRIDE + k);
                float4 h1 = *(const float4*)(hp + 1 * LSTM_STRIDE + k);
                float4 h2 = *(const float4*)(hp + 2 * LSTM_STRIDE + k);
                float4 h3 = *(const float4*)(hp + 3 * LSTM_STRIDE + k);
#define DOT4(J, RJ) \
                acc[J][0] += RJ.x*h0.x + RJ.y*h0.y + RJ.z*h0.z + RJ.w*h0.w; \
                acc[J][1] += RJ.x*h1.x + RJ.y*h1.y + RJ.z*h1.z + RJ.w*h1.w; \
                acc[J][2] += RJ.x*h2.x + RJ.y*h2.y + RJ.z*h2.z + RJ.w*h2.w; \
                acc[J][3] += RJ.x*h3.x + RJ.y*h3.y + RJ.z*h3.z + RJ.w*h3.w;
                DOT4(0, r0) DOT4(1, r1) DOT4(2, r2) DOT4(3, r3)
#undef DOT4
            }
#pragma unroll
            for (int j = 0; j < 4; j++)
#pragma unroll
                for (int i = 0; i < 4; i++)
                    z_part[ks][cq * 4 + j][bq * 4 + i] = acc[j][i];
        }
        __syncthreads();

        // ---- reduce 16 k-slices + xp ----
        {
            float z = xv;
#pragma unroll
            for (int s = 0; s < 16; s++) z += z_part[s][rc][rb];
            z_s[rc][rb] = z;
        }
        __syncthreads();

        // ---- gate math: 64 threads, one (u, b) each ----
        if (tid < 64) {
            int du = tid >> 4, b = tid & 15;
            float zi = z_s[0 * 4 + du][b], zf = z_s[1 * 4 + du][b];
            float zg = z_s[2 * 4 + du][b], zo = z_s[3 * 4 + du][b];
            float si = 1.f / (1.f + expf(-zi));
            float sf = 1.f / (1.f + expf(-zf));
            float so = 1.f / (1.f + expf(-zo));
            float c  = sf * c_s[du][b] + si * fmaxf(zg, 0.f);
            c_s[du][b] = c;
            float h = so * fmaxf(c, 0.f);
            d_hbuf[t & 1][b * 512 + u0 + du] = h;
            hs[((long)b * Ss + t) * 512 + u0 + du] = h;
        }
        __syncthreads();

        // ---- signal step t done ----
        if (tid == 0) {
            __threadfence();
            ((volatile int*)d_flags)[cta] = t + 1;
        }
    }
}

// ---------------- launch ------------------------------------------------------
extern "C" void kernel_launch(void* const* d_in, const int* in_sizes, int n_in,
                              void* d_out, int out_size)
{
    const float* emb   = (const float*)d_in[0];
    const float* Wq    = (const float*)d_in[1];
    const float* Wk    = (const float*)d_in[2];
    const float* Wv    = (const float*)d_in[3];
    const float* Wo    = (const float*)d_in[4];
    const float* gamma = (const float*)d_in[5];
    const float* beta  = (const float*)d_in[6];
    const float* lk    = (const float*)d_in[7];
    const float* lrk   = (const float*)d_in[8];
    const float* lb    = (const float*)d_in[9];

    float *q, *k, *v, *sc, *ctx, *proj, *y1, *xp, *hs;
    cudaGetSymbolAddress((void**)&q,    d_q);
    cudaGetSymbolAddress((void**)&k,    d_k);
    cudaGetSymbolAddress((void**)&v,    d_v);
    cudaGetSymbolAddress((void**)&sc,   d_scores);
    cudaGetSymbolAddress((void**)&ctx,  d_ctx);
    cudaGetSymbolAddress((void**)&proj, d_proj);
    cudaGetSymbolAddress((void**)&y1,   d_y1);
    cudaGetSymbolAddress((void**)&xp,   d_xp);
    cudaGetSymbolAddress((void**)&hs,   d_hs);

    const float sc_alpha = 0.044194173824159216f; // 1/sqrt(512)

    // Q, K, V
    sgemm<0><<<dim3(4, 128, 1), 256>>>(emb, Wq, q, nullptr, MR, Hh, Dd, 0, 0, 0, 1.f);
    sgemm<0><<<dim3(4, 128, 1), 256>>>(emb, Wk, k, nullptr, MR, Hh, Dd, 0, 0, 0, 1.f);
    sgemm<0><<<dim3(4, 128, 1), 256>>>(emb, Wv, v, nullptr, MR, Hh, Dd, 0, 0, 0, 1.f);

    // scores = Q K^T / sqrt(H)   (batched NT)
    sgemm<1><<<dim3(8, 8, 16), 256>>>(q, k, sc, nullptr, Ss, Ss, Hh,
                                      (long)Ss * Hh, (long)Ss * Hh, (long)Ss * Ss, sc_alpha);
    softmax_k<<<Bb * Ss, 256>>>(sc);

    // ctx = attn V   (batched NN)
    sgemm<0><<<dim3(4, 8, 16), 256>>>(sc, v, ctx, nullptr, Ss, Hh, Ss,
                                      (long)Ss * Ss, (long)Ss * Hh, (long)Ss * Hh, 1.f);

    // out-proj + residual LN
    sgemm<0><<<dim3(4, 128, 1), 256>>>(ctx, Wo, proj, nullptr, MR, Uu, Hh, 0, 0, 0, 1.f);
    ln_add_k<<<MR, 128>>>(proj, emb, gamma, beta, y1);

    // LSTM input projection (+bias)
    sgemm<0><<<dim3(16, 128, 1), 256>>>(y1, lk, xp, lb, MR, G4U, Uu, 0, 0, 0, 1.f);

    // persistent LSTM scan
    reset_k<<<32, 256>>>();
    cudaFuncSetAttribute(lstm_k, cudaFuncAttributeMaxDynamicSharedMemorySize, LSTM_DSMEM);
    lstm_k<<<LSTM_NCTA, 256, LSTM_DSMEM>>>(xp, lrk, hs);

    // final residual LN -> output
    ln_add_k<<<MR, 128>>>(hs, y1, gamma, beta, (float*)d_out);
}

// round 6
// speedup vs baseline: 1.4618x; 1.4618x over previous
#include <cuda_runtime.h>
#include <math.h>

#define Bb 16
#define Ss 1024
#define Dd 512
#define Hh 512
#define Uu 512
#define MR (Bb*Ss)        // 16384 rows
#define G4U (4*Uu)        // 2048

// ---------------- scratch (device globals; no allocations allowed) ----------
__device__ float d_q[MR*Hh];
__device__ float d_k[MR*Hh];
__device__ float d_v[MR*Hh];
__device__ float d_scores[(size_t)Bb*Ss*Ss];
__device__ float d_ctx[MR*Hh];
__device__ float d_proj[MR*Uu];
__device__ float d_y1[MR*Uu];
__device__ float d_xp[(size_t)MR*G4U];
__device__ float d_hs[MR*Uu];
__device__ float d_hbuf[2][Bb*Uu];
__device__ int   d_flags[128];

// ---------------- scoped acquire/release helpers (no CCTL.IVALL!) -----------
__device__ __forceinline__ void st_release_gpu(int* p, int v) {
    asm volatile("st.release.gpu.global.s32 [%0], %1;" :: "l"(p), "r"(v) : "memory");
}
__device__ __forceinline__ int ld_acquire_gpu(const int* p) {
    int v;
    asm volatile("ld.acquire.gpu.global.s32 %0, [%1];" : "=r"(v) : "l"(p) : "memory");
    return v;
}

// ---------------- generic fp32 SGEMM: C = alpha * A * op(B) (+bias) ---------
template<int TB>
__global__ __launch_bounds__(256) void sgemm(
    const float* __restrict__ Ag, const float* __restrict__ Bg,
    float* __restrict__ Cg, const float* __restrict__ bias,
    int M, int N, int K, long sA, long sB, long sC, float alpha)
{
    const float* A  = Ag + (long)blockIdx.z * sA;
    const float* Bm = Bg + (long)blockIdx.z * sB;
    float*       C  = Cg + (long)blockIdx.z * sC;

    __shared__ float As[8][128];
    __shared__ float Bs[8][128];

    int tid = threadIdx.x;
    int m0 = blockIdx.y * 128, n0 = blockIdx.x * 128;
    int tx = tid & 15, ty = tid >> 4;

    float acc[8][8];
#pragma unroll
    for (int i = 0; i < 8; i++)
#pragma unroll
        for (int j = 0; j < 8; j++) acc[i][j] = 0.f;

    int arow = tid >> 1, akc = (tid & 1) * 4;

    float4 av, bv;
    av = *(const float4*)&A[(long)(m0 + arow) * K + akc];
    if (TB == 0)
        bv = *(const float4*)&Bm[(long)(tid >> 5) * N + n0 + (tid & 31) * 4];
    else
        bv = *(const float4*)&Bm[(long)(n0 + (tid >> 1)) * K + (tid & 1) * 4];

    for (int k0 = 0; k0 < K; k0 += 8) {
        As[akc + 0][arow] = av.x; As[akc + 1][arow] = av.y;
        As[akc + 2][arow] = av.z; As[akc + 3][arow] = av.w;
        if (TB == 0) {
            *(float4*)&Bs[tid >> 5][(tid & 31) * 4] = bv;
        } else {
            int bn = tid >> 1, c0 = (tid & 1) * 4;
            Bs[c0 + 0][bn] = bv.x; Bs[c0 + 1][bn] = bv.y;
            Bs[c0 + 2][bn] = bv.z; Bs[c0 + 3][bn] = bv.w;
        }
        __syncthreads();

        int k1 = k0 + 8;
        if (k1 < K) {
            av = *(const float4*)&A[(long)(m0 + arow) * K + k1 + akc];
            if (TB == 0)
                bv = *(const float4*)&Bm[(long)(k1 + (tid >> 5)) * N + n0 + (tid & 31) * 4];
            else
                bv = *(const float4*)&Bm[(long)(n0 + (tid >> 1)) * K + k1 + (tid & 1) * 4];
        }

#pragma unroll
        for (int k = 0; k < 8; k++) {
            float a[8], b[8];
            *(float4*)&a[0] = *(const float4*)&As[k][ty * 4];
            *(float4*)&a[4] = *(const float4*)&As[k][64 + ty * 4];
            *(float4*)&b[0] = *(const float4*)&Bs[k][tx * 4];
            *(float4*)&b[4] = *(const float4*)&Bs[k][64 + tx * 4];
#pragma unroll
            for (int i = 0; i < 8; i++)
#pragma unroll
                for (int j = 0; j < 8; j++) acc[i][j] += a[i] * b[j];
        }
        __syncthreads();
    }

#pragma unroll
    for (int i = 0; i < 8; i++) {
        int r = m0 + ((i < 4) ? (ty * 4 + i) : (64 + ty * 4 + i - 4));
#pragma unroll
        for (int jh = 0; jh < 2; jh++) {
            int c = n0 + jh * 64 + tx * 4;
            float4 o;
            o.x = alpha * acc[i][jh * 4 + 0];
            o.y = alpha * acc[i][jh * 4 + 1];
            o.z = alpha * acc[i][jh * 4 + 2];
            o.w = alpha * acc[i][jh * 4 + 3];
            if (bias) {
                o.x += bias[c + 0]; o.y += bias[c + 1];
                o.z += bias[c + 2]; o.w += bias[c + 3];
            }
            *(float4*)&C[(long)r * N + c] = o;
        }
    }
}

// ---------------- softmax over rows of length 1024 ---------------------------
__global__ __launch_bounds__(256) void softmax_k(float* __restrict__ s)
{
    __shared__ float red[8];
    long row = blockIdx.x;
    float* p = s + row * 1024;
    int tid = threadIdx.x;
    float4 v = ((float4*)p)[tid];

    float m = fmaxf(fmaxf(v.x, v.y), fmaxf(v.z, v.w));
#pragma unroll
    for (int o = 16; o; o >>= 1) m = fmaxf(m, __shfl_xor_sync(~0u, m, o));
    if ((tid & 31) == 0) red[tid >> 5] = m;
    __syncthreads();
    m = red[0];
#pragma unroll
    for (int i = 1; i < 8; i++) m = fmaxf(m, red[i]);

    v.x = expf(v.x - m); v.y = expf(v.y - m);
    v.z = expf(v.z - m); v.w = expf(v.w - m);
    float su = v.x + v.y + v.z + v.w;
#pragma unroll
    for (int o = 16; o; o >>= 1) su += __shfl_xor_sync(~0u, su, o);
    __syncthreads();
    if ((tid & 31) == 0) red[tid >> 5] = su;
    __syncthreads();
    su = 0.f;
#pragma unroll
    for (int i = 0; i < 8; i++) su += red[i];
    float inv = 1.f / su;
    v.x *= inv; v.y *= inv; v.z *= inv; v.w *= inv;
    ((float4*)p)[tid] = v;
}

// ---------------- fused residual add + LayerNorm (row len 512) --------------
__global__ __launch_bounds__(128) void ln_add_k(
    const float* __restrict__ a, const float* __restrict__ b,
    const float* __restrict__ gamma, const float* __restrict__ beta,
    float* __restrict__ out)
{
    __shared__ float red[4];
    long row = blockIdx.x;
    int tid = threadIdx.x;
    float4 x = ((const float4*)(a + row * 512))[tid];
    float4 y = ((const float4*)(b + row * 512))[tid];
    x.x += y.x; x.y += y.y; x.z += y.z; x.w += y.w;

    float su = x.x + x.y + x.z + x.w;
#pragma unroll
    for (int o = 16; o; o >>= 1) su += __shfl_xor_sync(~0u, su, o);
    if ((tid & 31) == 0) red[tid >> 5] = su;
    __syncthreads();
    su = red[0] + red[1] + red[2] + red[3];
    float mu = su * (1.f / 512.f);

    float4 dx;
    dx.x = x.x - mu; dx.y = x.y - mu; dx.z = x.z - mu; dx.w = x.w - mu;
    float sq = dx.x * dx.x + dx.y * dx.y + dx.z * dx.z + dx.w * dx.w;
#pragma unroll
    for (int o = 16; o; o >>= 1) sq += __shfl_xor_sync(~0u, sq, o);
    __syncthreads();
    if ((tid & 31) == 0) red[tid >> 5] = sq;
    __syncthreads();
    sq = red[0] + red[1] + red[2] + red[3];
    float inv = rsqrtf(sq * (1.f / 512.f) + 1e-3f);

    float4 g = ((const float4*)gamma)[tid];
    float4 bt = ((const float4*)beta)[tid];
    float4 o4;
    o4.x = g.x * dx.x * inv + bt.x;
    o4.y = g.y * dx.y * inv + bt.y;
    o4.z = g.z * dx.z * inv + bt.z;
    o4.w = g.w * dx.w * inv + bt.w;
    ((float4*)(out + row * 512))[tid] = o4;
}

// ---------------- reset for persistent LSTM sync state ----------------------
__global__ void reset_k()
{
    int tid = threadIdx.x + blockIdx.x * blockDim.x;
    if (tid < Bb * Uu) { d_hbuf[0][tid] = 0.f; d_hbuf[1][tid] = 0.f; }
    if (tid < 128) d_flags[tid] = 0;
}

// ---------------- persistent LSTM scan --------------------------------------
// 128 CTAs x 256 threads (1 CTA/SM, single wave).
// CTA owns u's [cta*4, cta*4+4) -> 16 gate cols, ALL 16 batches.
// Barrier: per-CTA flag, release-store by producer, acquire-load spin by
// consumers. NO __threadfence anywhere -> no CCTL.IVALL L1 flush per step.
// h data moves through L2 only (__ldcg), so no stale-L1 hazard.
#define LSTM_NCTA 128
#define LSTM_STRIDE 516
#define LSTM_DSMEM (2 * 16 * LSTM_STRIDE * 4)   // Rs + h_s = 66048 B

__global__ __launch_bounds__(256) void lstm_k(
    const float* __restrict__ xp, const float* __restrict__ R,
    float* __restrict__ hs)
{
    extern __shared__ float sm[];
    float* Rs  = sm;                       // [16][516] k-major
    float* h_s = sm + 16 * LSTM_STRIDE;    // [16][516] k-major
    __shared__ float z_part[16][16][16];   // [ks][col][b]
    __shared__ float z_s[16][16];          // [col][b]
    __shared__ float c_s[4][17];

    const int tid = threadIdx.x;
    const int cta = blockIdx.x;
    const int u0  = cta * 4;

    // Load R slice transposed to k-major: Rs[c][k], c = g*4+du -> col g*512+u0+du
    for (int idx = tid; idx < 8192; idx += 256) {
        int c = idx & 15, k = idx >> 4;
        Rs[c * LSTM_STRIDE + k] = R[(long)k * 2048 + (c >> 2) * 512 + u0 + (c & 3)];
    }
    if (tid < 64) c_s[tid >> 4][tid & 15] = 0.f;

    const int cq = tid & 3;          // col quad: cols cq*4 .. cq*4+3
    const int bq = (tid >> 2) & 3;   // batch quad: b bq*4 .. bq*4+3
    const int ks = tid >> 4;         // 16 slices of 32 k
    const float* rp = Rs + (cq * 4) * LSTM_STRIDE + ks * 32;
    const float* hp = h_s + (bq * 4) * LSTM_STRIDE + ks * 32;

    // reducer identity: one (col, batch) per thread
    const int rc = tid >> 4;         // col 0..15
    const int rb = tid & 15;         // batch 0..15
    const float* xp_t = xp + (long)rb * Ss * 2048
                           + (rc >> 2) * 512 + u0 + (rc & 3);

    __syncthreads();

    for (int t = 0; t < 1024; t++) {
        // prefetch xp operand for this step (independent of barrier)
        float xv = __ldg(xp_t + (long)t * 2048);

        // ---- wait for all step-(t-1) h writes (acquire spin, no fence) ----
        if (t > 0) {
            if (tid < LSTM_NCTA) {
                while (ld_acquire_gpu(&d_flags[tid]) < t) { }
            }
            __syncthreads();
        }

        // ---- stage h_{t-1} (all 16 batches = 2048 float4) into smem ----
        {
            const float4* hg = (const float4*)(d_hbuf[(t + 1) & 1]);
#pragma unroll
            for (int j = 0; j < 8; j++) {
                int i = tid + j * 256;          // 0..2047 float4
                float4 v = __ldcg(hg + i);
                int b = i >> 7, k4 = (i & 127) * 4;
                *(float4*)(h_s + b * LSTM_STRIDE + k4) = v;
            }
        }
        __syncthreads();

        // ---- partial dots: 4 cols x 4 batches x 32 k per thread ----
        {
            float acc[4][4];
#pragma unroll
            for (int j = 0; j < 4; j++)
#pragma unroll
                for (int i = 0; i < 4; i++) acc[j][i] = 0.f;

#pragma unroll 2
            for (int k4 = 0; k4 < 8; k4++) {
                int k = k4 * 4;
                float4 r0 = *(const float4*)(rp + 0 * LSTM_STRIDE + k);
                float4 r1 = *(const float4*)(rp + 1 * LSTM_STRIDE + k);
                float4 r2 = *(const float4*)(rp + 2 * LSTM_STRIDE + k);
                float4 r3 = *(const float4*)(rp + 3 * LSTM_STRIDE + k);
                float4 h0 = *(const float4*)(hp + 0 * LSTM_STRIDE + k);
                float4 h1 = *(const float4*)(hp + 1 * LSTM_STRIDE + k);
                float4 h2 = *(const float4*)(hp + 2 * LSTM_STRIDE + k);
                float4 h3 = *(const float4*)(hp + 3 * LSTM_STRIDE + k);
#define DOT4(J, RJ) \
                acc[J][0] += RJ.x*h0.x + RJ.y*h0.y + RJ.z*h0.z + RJ.w*h0.w; \
                acc[J][1] += RJ.x*h1.x + RJ.y*h1.y + RJ.z*h1.z + RJ.w*h1.w; \
                acc[J][2] += RJ.x*h2.x + RJ.y*h2.y + RJ.z*h2.z + RJ.w*h2.w; \
                acc[J][3] += RJ.x*h3.x + RJ.y*h3.y + RJ.z*h3.z + RJ.w*h3.w;
                DOT4(0, r0) DOT4(1, r1) DOT4(2, r2) DOT4(3, r3)
#undef DOT4
            }
#pragma unroll
            for (int j = 0; j < 4; j++)
#pragma unroll
                for (int i = 0; i < 4; i++)
                    z_part[ks][cq * 4 + j][bq * 4 + i] = acc[j][i];
        }
        __syncthreads();

        // ---- reduce 16 k-slices + xp ----
        {
            float z = xv;
#pragma unroll
            for (int s = 0; s < 16; s++) z += z_part[s][rc][rb];
            z_s[rc][rb] = z;
        }
        __syncthreads();

        // ---- gate math: 64 threads, one (u, b) each ----
        if (tid < 64) {
            int du = tid >> 4, b = tid & 15;
            float zi = z_s[0 * 4 + du][b], zf = z_s[1 * 4 + du][b];
            float zg = z_s[2 * 4 + du][b], zo = z_s[3 * 4 + du][b];
            float si = 1.f / (1.f + expf(-zi));
            float sf = 1.f / (1.f + expf(-zf));
            float so = 1.f / (1.f + expf(-zo));
            float c  = sf * c_s[du][b] + si * fmaxf(zg, 0.f);
            c_s[du][b] = c;
            float h = so * fmaxf(c, 0.f);
            d_hbuf[t & 1][b * 512 + u0 + du] = h;
            hs[((long)b * Ss + t) * 512 + u0 + du] = h;
        }
        __syncthreads();

        // ---- signal step t done: release-store orders the h writes ----
        if (tid == 0) {
            st_release_gpu(&d_flags[cta], t + 1);
        }
    }
}

// ---------------- launch ------------------------------------------------------
extern "C" void kernel_launch(void* const* d_in, const int* in_sizes, int n_in,
                              void* d_out, int out_size)
{
    const float* emb   = (const float*)d_in[0];
    const float* Wq    = (const float*)d_in[1];
    const float* Wk    = (const float*)d_in[2];
    const float* Wv    = (const float*)d_in[3];
    const float* Wo    = (const float*)d_in[4];
    const float* gamma = (const float*)d_in[5];
    const float* beta  = (const float*)d_in[6];
    const float* lk    = (const float*)d_in[7];
    const float* lrk   = (const float*)d_in[8];
    const float* lb    = (const float*)d_in[9];

    float *q, *k, *v, *sc, *ctx, *proj, *y1, *xp, *hs;
    cudaGetSymbolAddress((void**)&q,    d_q);
    cudaGetSymbolAddress((void**)&k,    d_k);
    cudaGetSymbolAddress((void**)&v,    d_v);
    cudaGetSymbolAddress((void**)&sc,   d_scores);
    cudaGetSymbolAddress((void**)&ctx,  d_ctx);
    cudaGetSymbolAddress((void**)&proj, d_proj);
    cudaGetSymbolAddress((void**)&y1,   d_y1);
    cudaGetSymbolAddress((void**)&xp,   d_xp);
    cudaGetSymbolAddress((void**)&hs,   d_hs);

    const float sc_alpha = 0.044194173824159216f; // 1/sqrt(512)

    // Q, K, V
    sgemm<0><<<dim3(4, 128, 1), 256>>>(emb, Wq, q, nullptr, MR, Hh, Dd, 0, 0, 0, 1.f);
    sgemm<0><<<dim3(4, 128, 1), 256>>>(emb, Wk, k, nullptr, MR, Hh, Dd, 0, 0, 0, 1.f);
    sgemm<0><<<dim3(4, 128, 1), 256>>>(emb, Wv, v, nullptr, MR, Hh, Dd, 0, 0, 0, 1.f);

    // scores = Q K^T / sqrt(H)   (batched NT)
    sgemm<1><<<dim3(8, 8, 16), 256>>>(q, k, sc, nullptr, Ss, Ss, Hh,
                                      (long)Ss * Hh, (long)Ss * Hh, (long)Ss * Ss, sc_alpha);
    softmax_k<<<Bb * Ss, 256>>>(sc);

    // ctx = attn V   (batched NN)
    sgemm<0><<<dim3(4, 8, 16), 256>>>(sc, v, ctx, nullptr, Ss, Hh, Ss,
                                      (long)Ss * Ss, (long)Ss * Hh, (long)Ss * Hh, 1.f);

    // out-proj + residual LN
    sgemm<0><<<dim3(4, 128, 1), 256>>>(ctx, Wo, proj, nullptr, MR, Uu, Hh, 0, 0, 0, 1.f);
    ln_add_k<<<MR, 128>>>(proj, emb, gamma, beta, y1);

    // LSTM input projection (+bias)
    sgemm<0><<<dim3(16, 128, 1), 256>>>(y1, lk, xp, lb, MR, G4U, Uu, 0, 0, 0, 1.f);

    // persistent LSTM scan
    reset_k<<<32, 256>>>();
    cudaFuncSetAttribute(lstm_k, cudaFuncAttributeMaxDynamicSharedMemorySize, LSTM_DSMEM);
    lstm_k<<<LSTM_NCTA, 256, LSTM_DSMEM>>>(xp, lrk, hs);

    // final residual LN -> output
    ln_add_k<<<MR, 128>>>(hs, y1, gamma, beta, (float*)d_out);
}